// round 1
// baseline (speedup 1.0000x reference)
#include <cuda_runtime.h>
#include <mma.h>

using namespace nvcuda;

#define DIM   1024
#define BATCH 8
#define SEQ   2048
#define MTOT  (BATCH*SEQ)   // 16384

#define BM 128
#define BN 64
#define BK 32
#define BKP 40              // pad to keep 32B alignment for wmma loads
#define BNP 72
#define NTHREADS 256

#define SA_SZ (BM*BKP)      // 5120 floats
#define SMEM_FLOATS 8192    // >= max(SA+SB, BM*BN)

// Scratch (allocation-free rule: __device__ globals)
__device__ float g_Q[(size_t)MTOT * DIM];
__device__ float g_K[(size_t)MTOT * DIM];
__device__ float g_V[(size_t)MTOT * DIM];
__device__ float g_S[(size_t)BATCH * SEQ * SEQ];

// Generic tiled TF32 GEMM.
//  B_IS_NK=true : C = A(MxK) * B(NxK)^T   (projections, scores)
//  B_IS_NK=false: C = A(MxK) * B(KxN)     (P @ V)
//  CAUSAL_SKIP: skip blocks entirely above the diagonal (scores)
//  KCAUSAL:     limit K loop to m0+BM (P rows are zero beyond that — PV)
template<bool B_IS_NK, bool CAUSAL_SKIP, bool KCAUSAL>
__global__ __launch_bounds__(NTHREADS)
void gemm_kernel(const float* __restrict__ A, const float* __restrict__ Bm,
                 const float* __restrict__ ctx, const float* __restrict__ bias,
                 float* __restrict__ C,
                 int M, int N, int K, int lda, int ldb, int ldc,
                 long strideA, long strideB, long strideC, float scale)
{
    __shared__ float smem[SMEM_FLOATS];
    float* sA = smem;
    float* sB = smem + SA_SZ;

    const int m0 = blockIdx.x * BM;
    const int n0 = blockIdx.y * BN;
    if (CAUSAL_SKIP && n0 >= m0 + BM) return;

    const int bz = blockIdx.z;
    const float* Ab = A  + (size_t)bz * strideA;
    const float* Bb = Bm + (size_t)bz * strideB;
    float*       Cb = C  + (size_t)bz * strideC;

    const int kEnd = KCAUSAL ? min(K, m0 + BM) : K;

    const int tid   = threadIdx.x;
    const int warp  = tid >> 5;
    const int warpM = warp >> 1;   // 0..3 -> 32 rows each
    const int warpN = warp & 1;    // 0..1 -> 32 cols each

    wmma::fragment<wmma::accumulator, 16, 16, 8, float> acc[2][2];
    #pragma unroll
    for (int i = 0; i < 2; i++)
        #pragma unroll
        for (int j = 0; j < 2; j++)
            wmma::fill_fragment(acc[i][j], 0.0f);

    for (int k0 = 0; k0 < kEnd; k0 += BK) {
        // ---- load A tile (BM x BK), fuse +ctx ----
        {
            const int r  = tid >> 3;          // 0..31
            const int c4 = (tid & 7) << 2;    // 0,4,..,28
            float4 cv = make_float4(0.f, 0.f, 0.f, 0.f);
            if (ctx) cv = *reinterpret_cast<const float4*>(ctx + k0 + c4);
            #pragma unroll
            for (int rr = 0; rr < BM; rr += 32) {
                float4 av = *reinterpret_cast<const float4*>(
                    Ab + (size_t)(m0 + r + rr) * lda + k0 + c4);
                av.x += cv.x; av.y += cv.y; av.z += cv.z; av.w += cv.w;
                float* d = &sA[(r + rr) * BKP + c4];
                d[0] = av.x; d[1] = av.y; d[2] = av.z; d[3] = av.w;
            }
        }
        // ---- load B tile ----
        if (B_IS_NK) {
            // rows of B are N entries, K contiguous -> store col-major-ish [BN][BKP]
            const int r  = tid >> 3;
            const int c4 = (tid & 7) << 2;
            #pragma unroll
            for (int rr = 0; rr < BN; rr += 32) {
                float4 bv = *reinterpret_cast<const float4*>(
                    Bb + (size_t)(n0 + r + rr) * ldb + k0 + c4);
                float* d = &sB[(r + rr) * BKP + c4];
                d[0] = bv.x; d[1] = bv.y; d[2] = bv.z; d[3] = bv.w;
            }
        } else {
            // B row-major [K][N] -> store [BK][BNP]
            const int r  = tid >> 4;           // 0..15
            const int c4 = (tid & 15) << 2;    // 0..60
            #pragma unroll
            for (int rr = 0; rr < BK; rr += 16) {
                float4 bv = *reinterpret_cast<const float4*>(
                    Bb + (size_t)(k0 + r + rr) * ldb + n0 + c4);
                float* d = &sB[(r + rr) * BNP + c4];
                d[0] = bv.x; d[1] = bv.y; d[2] = bv.z; d[3] = bv.w;
            }
        }
        __syncthreads();

        #pragma unroll
        for (int kk = 0; kk < BK; kk += 8) {
            wmma::fragment<wmma::matrix_a, 16, 16, 8, wmma::precision::tf32, wmma::row_major> af[2];
            #pragma unroll
            for (int i = 0; i < 2; i++) {
                wmma::load_matrix_sync(af[i], &sA[(warpM * 32 + i * 16) * BKP + kk], BKP);
                #pragma unroll
                for (int t = 0; t < af[i].num_elements; t++)
                    af[i].x[t] = wmma::__float_to_tf32(af[i].x[t]);
            }
            if (B_IS_NK) {
                wmma::fragment<wmma::matrix_b, 16, 16, 8, wmma::precision::tf32, wmma::col_major> bf[2];
                #pragma unroll
                for (int j = 0; j < 2; j++) {
                    wmma::load_matrix_sync(bf[j], &sB[(warpN * 32 + j * 16) * BKP + kk], BKP);
                    #pragma unroll
                    for (int t = 0; t < bf[j].num_elements; t++)
                        bf[j].x[t] = wmma::__float_to_tf32(bf[j].x[t]);
                }
                #pragma unroll
                for (int i = 0; i < 2; i++)
                    #pragma unroll
                    for (int j = 0; j < 2; j++)
                        wmma::mma_sync(acc[i][j], af[i], bf[j], acc[i][j]);
            } else {
                wmma::fragment<wmma::matrix_b, 16, 16, 8, wmma::precision::tf32, wmma::row_major> bf[2];
                #pragma unroll
                for (int j = 0; j < 2; j++) {
                    wmma::load_matrix_sync(bf[j], &sB[kk * BNP + warpN * 32 + j * 16], BNP);
                    #pragma unroll
                    for (int t = 0; t < bf[j].num_elements; t++)
                        bf[j].x[t] = wmma::__float_to_tf32(bf[j].x[t]);
                }
                #pragma unroll
                for (int i = 0; i < 2; i++)
                    #pragma unroll
                    for (int j = 0; j < 2; j++)
                        wmma::mma_sync(acc[i][j], af[i], bf[j], acc[i][j]);
            }
        }
        __syncthreads();
    }

    // ---- epilogue: stage in smem, fused scale + bias, vectorized store ----
    float* sC = smem;  // safe: synced after last mma
    #pragma unroll
    for (int i = 0; i < 2; i++)
        #pragma unroll
        for (int j = 0; j < 2; j++)
            wmma::store_matrix_sync(&sC[(warpM * 32 + i * 16) * BN + warpN * 32 + j * 16],
                                    acc[i][j], BN, wmma::mem_row_major);
    __syncthreads();

    {
        const int r  = tid >> 4;           // 0..15
        const int c4 = (tid & 15) << 2;    // 0..60
        float4 bb = make_float4(0.f, 0.f, 0.f, 0.f);
        if (bias) bb = *reinterpret_cast<const float4*>(bias + n0 + c4);
        #pragma unroll
        for (int rr = 0; rr < BM; rr += 16) {
            float4 cv = *reinterpret_cast<float4*>(&sC[(r + rr) * BN + c4]);
            cv.x = cv.x * scale + bb.x;
            cv.y = cv.y * scale + bb.y;
            cv.z = cv.z * scale + bb.z;
            cv.w = cv.w * scale + bb.w;
            *reinterpret_cast<float4*>(Cb + (size_t)(m0 + r + rr) * ldc + n0 + c4) = cv;
        }
    }
}

// Causal row softmax: one block per (b, i) row; row cached in smem.
// Writes zeros for j in (i, next 128 boundary) so the PV GEMM (k-limit m0+128)
// never reads undefined data.
__global__ __launch_bounds__(256)
void softmax_kernel(float* __restrict__ S)
{
    __shared__ float buf[SEQ];
    __shared__ float red[8];
    const int row = blockIdx.x;          // 0..MTOT-1
    const int b   = row >> 11;           // /SEQ
    const int i   = row & (SEQ - 1);
    float* p = S + ((size_t)b * SEQ + i) * SEQ;
    const int len = i + 1;
    const int tid  = threadIdx.x;
    const int lane = tid & 31;
    const int w    = tid >> 5;

    float m = -1e30f;
    for (int j = tid; j < len; j += 256) { float v = p[j]; buf[j] = v; m = fmaxf(m, v); }
    #pragma unroll
    for (int o = 16; o; o >>= 1) m = fmaxf(m, __shfl_xor_sync(0xffffffffu, m, o));
    if (lane == 0) red[w] = m;
    __syncthreads();
    if (tid == 0) {
        float mm = red[0];
        #pragma unroll
        for (int x = 1; x < 8; x++) mm = fmaxf(mm, red[x]);
        red[0] = mm;
    }
    __syncthreads();
    m = red[0];
    __syncthreads();  // all threads read red[0] before it is reused

    float s = 0.f;
    for (int j = tid; j < len; j += 256) { float e = __expf(buf[j] - m); buf[j] = e; s += e; }
    #pragma unroll
    for (int o = 16; o; o >>= 1) s += __shfl_xor_sync(0xffffffffu, s, o);
    if (lane == 0) red[w] = s;
    __syncthreads();
    if (tid == 0) {
        float ss = red[0];
        #pragma unroll
        for (int x = 1; x < 8; x++) ss += red[x];
        red[0] = ss;
    }
    __syncthreads();
    const float inv = 1.0f / red[0];

    const int zend = min(SEQ, ((i >> 7) + 1) << 7);   // zero-fill to 128 boundary
    for (int j = tid; j < zend; j += 256) p[j] = (j < len) ? buf[j] * inv : 0.0f;
}

extern "C" void kernel_launch(void* const* d_in, const int* in_sizes, int n_in,
                              void* d_out, int out_size)
{
    const float* query = (const float*)d_in[0];
    const float* key   = (const float*)d_in[1];
    const float* value = (const float*)d_in[2];
    const float* ctx   = (const float*)d_in[3];
    const float* Wq    = (const float*)d_in[4];
    const float* bq    = (const float*)d_in[5];
    const float* Wk    = (const float*)d_in[6];
    const float* bk    = (const float*)d_in[7];
    const float* Wv    = (const float*)d_in[8];
    const float* bv    = (const float*)d_in[9];
    float* out = (float*)d_out;

    float *pQ, *pK, *pV, *pS;
    cudaGetSymbolAddress((void**)&pQ, g_Q);
    cudaGetSymbolAddress((void**)&pK, g_K);
    cudaGetSymbolAddress((void**)&pV, g_V);
    cudaGetSymbolAddress((void**)&pS, g_S);

    dim3 blk(NTHREADS);

    // 1-3) projections: (x [+ctx]) @ W^T + b
    dim3 gp(MTOT / BM, DIM / BN, 1);
    gemm_kernel<true,  false, false><<<gp, blk>>>(query, Wq, ctx,     bq, pQ,
        MTOT, DIM, DIM, DIM, DIM, DIM, 0, 0, 0, 1.0f);
    gemm_kernel<true,  false, false><<<gp, blk>>>(key,   Wk, ctx,     bk, pK,
        MTOT, DIM, DIM, DIM, DIM, DIM, 0, 0, 0, 1.0f);
    gemm_kernel<true,  false, false><<<gp, blk>>>(value, Wv, nullptr, bv, pV,
        MTOT, DIM, DIM, DIM, DIM, DIM, 0, 0, 0, 1.0f);

    // 4) scores = Q @ K^T * D^-0.5 (causal block skip), batched over B
    dim3 gs(SEQ / BM, SEQ / BN, BATCH);
    const float scale = 0.03125f;  // 1024^-0.5
    gemm_kernel<true,  true,  false><<<gs, blk>>>(pQ, pK, nullptr, nullptr, pS,
        SEQ, SEQ, DIM, DIM, DIM, SEQ,
        (long)SEQ * DIM, (long)SEQ * DIM, (long)SEQ * SEQ, scale);

    // 5) causal softmax rows
    softmax_kernel<<<MTOT, 256>>>(pS);

    // 6) out = P @ V (k-limited by causality), batched over B
    dim3 gv(SEQ / BM, DIM / BN, BATCH);
    gemm_kernel<false, false, true ><<<gv, blk>>>(pS, pV, nullptr, nullptr, out,
        SEQ, DIM, SEQ, SEQ, DIM, DIM,
        (long)SEQ * SEQ, (long)SEQ * DIM, (long)SEQ * DIM, 1.0f);
}

// round 3
// speedup vs baseline: 1.1222x; 1.1222x over previous
#include <cuda_runtime.h>
#include <cstdint>
#include <mma.h>

using namespace nvcuda;

#define DIM   1024
#define BATCH 8
#define SEQ   2048
#define MTOT  (BATCH*SEQ)   // 16384

#define BM 128
#define BN 128
#define BK 32
#define AKP 40              // padded lda for [128][BK] tiles (160B rows, 16B aligned)
#define BNP 136             // padded ldb for [BK][128] tiles (544B rows, 16B aligned)
#define STAGE_FLOATS 10240  // A(128*40) + B(max 128*40) per stage
#define SMEM_BYTES   81920  // 2 stages; epilogue reuses first 64KB

// Scratch (allocation-free rule: __device__ globals)
__device__ float g_Q[(size_t)MTOT * DIM];
__device__ float g_K[(size_t)MTOT * DIM];
__device__ float g_V[(size_t)MTOT * DIM];
__device__ float g_S[(size_t)BATCH * SEQ * SEQ];   // also staging for rounded X/W
__device__ float g_bias[2 * DIM];

__device__ __forceinline__ float tf32r(float x) {
    asm("cvt.rna.tf32.f32 %0, %1;" : "=f"(x) : "f"(x));
    return x;
}
__device__ __forceinline__ void cpa16(unsigned int saddr, const void* gaddr) {
    asm volatile("cp.async.cg.shared.global [%0], [%1], 16;" :: "r"(saddr), "l"(gaddr));
}

// Tiled TF32 GEMM, cp.async double-buffered, NO in-loop conversions
// (all operands pre-rounded to tf32).
//  B_IS_NK=true : C = A(MxK) * B(NxK)^T
//  B_IS_NK=false: C = A(MxK) * B(KxN)
//  CAUSAL_SKIP  : skip blocks strictly above the diagonal (scores)
//  KCAUSAL      : limit K loop to m0+BM (PV; probs zero-filled to boundary)
template<bool B_IS_NK, bool CAUSAL_SKIP, bool KCAUSAL>
__global__ __launch_bounds__(256)
void gemm2(const float* __restrict__ A, const float* __restrict__ Bm,
           const float* __restrict__ bias, float* __restrict__ C,
           int lda, int ldb, int ldc, int K,
           long strideA, long strideB, long strideC,
           float scale, int roundOut)
{
    extern __shared__ float sm[];

    const int m0 = blockIdx.x * BM;
    const int n0 = blockIdx.y * BN;
    if (CAUSAL_SKIP && n0 > m0) return;

    const int bz = blockIdx.z;
    const float* Ab = A  + (size_t)bz * strideA;
    const float* Bb = Bm + (size_t)bz * strideB;
    float*       Cb = C  + (size_t)bz * strideC;

    const int kEnd = KCAUSAL ? (m0 + BM) : K;
    const int nk   = kEnd / BK;

    const int tid  = threadIdx.x;
    const int warp = tid >> 5;
    const int wm   = warp >> 1;    // 0..3  -> 32 rows
    const int wn   = warp & 1;     // 0..1  -> 64 cols

    const unsigned int smBase = (unsigned int)__cvta_generic_to_shared(sm);

    wmma::fragment<wmma::accumulator, 16, 16, 8, float> acc[2][4];
    #pragma unroll
    for (int i = 0; i < 2; i++)
        #pragma unroll
        for (int j = 0; j < 4; j++)
            wmma::fill_fragment(acc[i][j], 0.0f);

    // async-load one stage (all 256 threads participate, no divergence)
    auto loadStage = [&](int st, int k0) {
        const unsigned int dA = smBase + (unsigned int)(st * STAGE_FLOATS) * 4u;
        const unsigned int dB = dA + 5120u * 4u;
        {   // A tile: 128 x 32
            const int r  = tid >> 3;
            const int c4 = (tid & 7) << 2;
            #pragma unroll
            for (int rr = 0; rr < BM; rr += 32)
                cpa16(dA + (unsigned int)((r + rr) * AKP + c4) * 4u,
                      Ab + (size_t)(m0 + r + rr) * lda + k0 + c4);
        }
        if (B_IS_NK) {  // B tile: 128 rows (N) x 32 (K)
            const int r  = tid >> 3;
            const int c4 = (tid & 7) << 2;
            #pragma unroll
            for (int rr = 0; rr < BN; rr += 32)
                cpa16(dB + (unsigned int)((r + rr) * AKP + c4) * 4u,
                      Bb + (size_t)(n0 + r + rr) * ldb + k0 + c4);
        } else {        // B tile: 32 rows (K) x 128 (N)
            const int r  = tid >> 5;
            const int c4 = (tid & 31) << 2;
            #pragma unroll
            for (int rr = 0; rr < BK; rr += 8)
                cpa16(dB + (unsigned int)((r + rr) * BNP + c4) * 4u,
                      Bb + (size_t)(k0 + r + rr) * ldb + n0 + c4);
        }
        asm volatile("cp.async.commit_group;");
    };

    loadStage(0, 0);

    for (int kt = 0; kt < nk; kt++) {
        if (kt + 1 < nk) {
            loadStage((kt + 1) & 1, (kt + 1) * BK);
            asm volatile("cp.async.wait_group 1;");
        } else {
            asm volatile("cp.async.wait_group 0;");
        }
        __syncthreads();

        const float* a0 = sm + (kt & 1) * STAGE_FLOATS;
        const float* b0 = a0 + 5120;

        #pragma unroll
        for (int kk = 0; kk < BK; kk += 8) {
            wmma::fragment<wmma::matrix_a, 16, 16, 8, wmma::precision::tf32, wmma::row_major> af[2];
            #pragma unroll
            for (int i = 0; i < 2; i++)
                wmma::load_matrix_sync(af[i], a0 + (wm * 32 + i * 16) * AKP + kk, AKP);

            if (B_IS_NK) {
                wmma::fragment<wmma::matrix_b, 16, 16, 8, wmma::precision::tf32, wmma::col_major> bf[4];
                #pragma unroll
                for (int j = 0; j < 4; j++)
                    wmma::load_matrix_sync(bf[j], b0 + (wn * 64 + j * 16) * AKP + kk, AKP);
                #pragma unroll
                for (int i = 0; i < 2; i++)
                    #pragma unroll
                    for (int j = 0; j < 4; j++)
                        wmma::mma_sync(acc[i][j], af[i], bf[j], acc[i][j]);
            } else {
                wmma::fragment<wmma::matrix_b, 16, 16, 8, wmma::precision::tf32, wmma::row_major> bf[4];
                #pragma unroll
                for (int j = 0; j < 4; j++)
                    wmma::load_matrix_sync(bf[j], b0 + kk * BNP + wn * 64 + j * 16, BNP);
                #pragma unroll
                for (int i = 0; i < 2; i++)
                    #pragma unroll
                    for (int j = 0; j < 4; j++)
                        wmma::mma_sync(acc[i][j], af[i], bf[j], acc[i][j]);
            }
        }
        __syncthreads();
    }

    // epilogue: stage to smem, fused scale+bias (+optional tf32 round), float4 stores
    float* sC = sm;
    #pragma unroll
    for (int i = 0; i < 2; i++)
        #pragma unroll
        for (int j = 0; j < 4; j++)
            wmma::store_matrix_sync(sC + (wm * 32 + i * 16) * BN + wn * 64 + j * 16,
                                    acc[i][j], BN, wmma::mem_row_major);
    __syncthreads();

    {
        const int r  = tid >> 5;            // 0..7
        const int c4 = (tid & 31) << 2;     // 0..124
        float4 bb = make_float4(0.f, 0.f, 0.f, 0.f);
        if (bias) bb = *reinterpret_cast<const float4*>(bias + n0 + c4);
        #pragma unroll
        for (int rr = 0; rr < BM; rr += 8) {
            float4 v = *reinterpret_cast<float4*>(&sC[(r + rr) * BN + c4]);
            v.x = v.x * scale + bb.x;
            v.y = v.y * scale + bb.y;
            v.z = v.z * scale + bb.z;
            v.w = v.w * scale + bb.w;
            if (roundOut) {
                v.x = tf32r(v.x); v.y = tf32r(v.y);
                v.z = tf32r(v.z); v.w = tf32r(v.w);
            }
            *reinterpret_cast<float4*>(Cb + (size_t)(m0 + r + rr) * ldc + n0 + c4) = v;
        }
    }
}

// elementwise round-to-tf32 (n4 = #float4)
__global__ __launch_bounds__(256)
void round_k(const float* __restrict__ in, float* __restrict__ out, int n4)
{
    int i = blockIdx.x * 256 + threadIdx.x;
    if (i < n4) {
        float4 v = reinterpret_cast<const float4*>(in)[i];
        v.x = tf32r(v.x); v.y = tf32r(v.y); v.z = tf32r(v.z); v.w = tf32r(v.w);
        reinterpret_cast<float4*>(out)[i] = v;
    }
}

// bout[e] = b[e] + dot(W[e,:], ctx)   — folds the context bias into the GEMM bias
__global__ __launch_bounds__(256)
void bias_prep(const float* __restrict__ W, const float* __restrict__ b,
               const float* __restrict__ ctx, float* __restrict__ bout)
{
    __shared__ float red[8];
    const int e = blockIdx.x;
    const int tid = threadIdx.x, lane = tid & 31, w = tid >> 5;
    float s = 0.f;
    for (int d = tid; d < DIM; d += 256) s += W[(size_t)e * DIM + d] * ctx[d];
    #pragma unroll
    for (int o = 16; o; o >>= 1) s += __shfl_xor_sync(0xffffffffu, s, o);
    if (lane == 0) red[w] = s;
    __syncthreads();
    if (tid == 0) {
        float t = 0.f;
        #pragma unroll
        for (int x = 0; x < 8; x++) t += red[x];
        bout[e] = b[e] + t;
    }
}

// Causal row softmax; writes tf32-rounded probs, zero-fills to next 128 boundary
__global__ __launch_bounds__(256)
void softmax_kernel(float* __restrict__ S)
{
    __shared__ float buf[SEQ];
    __shared__ float red[8];
    const int row = blockIdx.x;
    const int b   = row >> 11;
    const int i   = row & (SEQ - 1);
    float* p = S + ((size_t)b * SEQ + i) * SEQ;
    const int len = i + 1;
    const int tid = threadIdx.x, lane = tid & 31, w = tid >> 5;

    float m = -1e30f;
    for (int j = tid; j < len; j += 256) { float v = p[j]; buf[j] = v; m = fmaxf(m, v); }
    #pragma unroll
    for (int o = 16; o; o >>= 1) m = fmaxf(m, __shfl_xor_sync(0xffffffffu, m, o));
    if (lane == 0) red[w] = m;
    __syncthreads();
    if (tid == 0) {
        float mm = red[0];
        #pragma unroll
        for (int x = 1; x < 8; x++) mm = fmaxf(mm, red[x]);
        red[0] = mm;
    }
    __syncthreads();
    m = red[0];
    __syncthreads();

    float s = 0.f;
    for (int j = tid; j < len; j += 256) { float e = __expf(buf[j] - m); buf[j] = e; s += e; }
    #pragma unroll
    for (int o = 16; o; o >>= 1) s += __shfl_xor_sync(0xffffffffu, s, o);
    if (lane == 0) red[w] = s;
    __syncthreads();
    if (tid == 0) {
        float ss = red[0];
        #pragma unroll
        for (int x = 1; x < 8; x++) ss += red[x];
        red[0] = ss;
    }
    __syncthreads();
    const float inv = 1.0f / red[0];

    const int zend = min(SEQ, ((i >> 7) + 1) << 7);
    for (int j = tid; j < zend; j += 256)
        p[j] = (j < len) ? tf32r(buf[j] * inv) : 0.0f;
}

extern "C" void kernel_launch(void* const* d_in, const int* in_sizes, int n_in,
                              void* d_out, int out_size)
{
    const float* query = (const float*)d_in[0];
    const float* key   = (const float*)d_in[1];
    const float* value = (const float*)d_in[2];
    const float* ctx   = (const float*)d_in[3];
    const float* Wq    = (const float*)d_in[4];
    const float* bq    = (const float*)d_in[5];
    const float* Wk    = (const float*)d_in[6];
    const float* bk    = (const float*)d_in[7];
    const float* Wv    = (const float*)d_in[8];
    const float* bv    = (const float*)d_in[9];
    float* out = (float*)d_out;

    float *pQ, *pK, *pV, *pS, *pBias;
    cudaGetSymbolAddress((void**)&pQ, g_Q);
    cudaGetSymbolAddress((void**)&pK, g_K);
    cudaGetSymbolAddress((void**)&pV, g_V);
    cudaGetSymbolAddress((void**)&pS, g_S);
    cudaGetSymbolAddress((void**)&pBias, g_bias);

    // staging inside g_S (free until the scores GEMM runs)
    float* pX = pS;                                   // rounded inputs (16.7M floats)
    float* pW = pS + (size_t)18 * 1024 * 1024;        // rounded weights (1M floats)

    cudaFuncSetAttribute(gemm2<true,  false, false>, cudaFuncAttributeMaxDynamicSharedMemorySize, SMEM_BYTES);
    cudaFuncSetAttribute(gemm2<true,  true,  false>, cudaFuncAttributeMaxDynamicSharedMemorySize, SMEM_BYTES);
    cudaFuncSetAttribute(gemm2<false, false, true >, cudaFuncAttributeMaxDynamicSharedMemorySize, SMEM_BYTES);

    const int nX4 = MTOT * DIM / 4;                   // 4,194,304
    const int nW4 = DIM * DIM / 4;                    // 262,144

    // fold ctx into q/k biases
    bias_prep<<<DIM, 256>>>(Wq, bq, ctx, pBias);
    bias_prep<<<DIM, 256>>>(Wk, bk, ctx, pBias + DIM);

    dim3 gp(MTOT / BM, DIM / BN, 1);

    // Q projection
    round_k<<<nX4 / 256, 256>>>(query, pX, nX4);
    round_k<<<nW4 / 256, 256>>>(Wq, pW, nW4);
    gemm2<true, false, false><<<gp, 256, SMEM_BYTES>>>(pX, pW, pBias, pQ,
        DIM, DIM, DIM, DIM, 0, 0, 0, 1.0f, 1);

    // K projection
    round_k<<<nX4 / 256, 256>>>(key, pX, nX4);
    round_k<<<nW4 / 256, 256>>>(Wk, pW, nW4);
    gemm2<true, false, false><<<gp, 256, SMEM_BYTES>>>(pX, pW, pBias + DIM, pK,
        DIM, DIM, DIM, DIM, 0, 0, 0, 1.0f, 1);

    // V projection (no ctx)
    round_k<<<nX4 / 256, 256>>>(value, pX, nX4);
    round_k<<<nW4 / 256, 256>>>(Wv, pW, nW4);
    gemm2<true, false, false><<<gp, 256, SMEM_BYTES>>>(pX, pW, bv, pV,
        DIM, DIM, DIM, DIM, 0, 0, 0, 1.0f, 1);

    // scores = Q @ K^T * scale, causal block skip, batched over B
    dim3 gs(SEQ / BM, SEQ / BN, BATCH);
    gemm2<true, true, false><<<gs, 256, SMEM_BYTES>>>(pQ, pK, nullptr, pS,
        DIM, DIM, SEQ, DIM,
        (long)SEQ * DIM, (long)SEQ * DIM, (long)SEQ * SEQ, 0.03125f, 0);

    // causal softmax (rounds probs to tf32)
    softmax_kernel<<<MTOT, 256>>>(pS);

    // out = P @ V (k-limited by causality)
    dim3 gv(SEQ / BM, DIM / BN, BATCH);
    gemm2<false, false, true><<<gv, 256, SMEM_BYTES>>>(pS, pV, nullptr, out,
        SEQ, DIM, DIM, DIM,
        (long)SEQ * SEQ, (long)SEQ * DIM, (long)SEQ * DIM, 1.0f, 0);
}

// round 5
// speedup vs baseline: 4.1583x; 3.7055x over previous
#include <cuda_runtime.h>
#include <cstdint>
#include <cuda_fp16.h>
#include <mma.h>

using namespace nvcuda;

#define DIM   1024
#define BATCH 8
#define SEQ   2048
#define MTOT  (BATCH*SEQ)   // 16384

#define BM 128
#define BN 128
#define BKH 64              // K halves per tile (128 bytes/row)
#define KP  72              // padded smem row (halves), multiple of 8
#define SC_LD 132           // epilogue fp32 staging ld (multiple of 4)
#define STAGE_HALVES (2*BM*KP)        // A + B per stage = 18432 halves
#define SMEM_BYTES (2*STAGE_HALVES*2) // 73728 B (epilogue reuse: 128*132*4=67584)
#define NTH 256

// ---------------- scratch (__device__ globals; no allocation) ----------------
__device__ float  g_S [(size_t)BATCH * SEQ * SEQ];   // fp32 scores
__device__ __half g_hP[(size_t)BATCH * SEQ * SEQ];   // fp16 probs
__device__ __half g_hQ[(size_t)MTOT * DIM];
__device__ __half g_hK[(size_t)MTOT * DIM];
__device__ __half g_hVt[(size_t)DIM * MTOT];         // V projection TRANSPOSED [e][b*SEQ+s]
__device__ __half g_hX[(size_t)MTOT * DIM];          // staging: fp16 input
__device__ __half g_hW[(size_t)DIM * DIM];           // staging: fp16 weight
__device__ float  g_bias[2 * DIM];

__device__ __forceinline__ void cpa16(unsigned saddr, const void* gaddr) {
    asm volatile("cp.async.cg.shared.global [%0], [%1], 16;" :: "r"(saddr), "l"(gaddr));
}

// ---------------- fp16 tensor-core GEMM ----------------
// C(M,N) = A(M,K) * B(N,K)^T ; A,B fp16 row-major-K, fp32 accumulate.
//  CAUSAL_SKIP : skip blocks strictly above the diagonal (scores)
//  KCAUSAL     : limit K loop to m0+128 (PV; probs zero-filled to boundary)
//  TRANS_OUT   : write C transposed (V projection -> Vt[n][m])
//  OUT_HALF    : output fp16 (projections) else fp32
template<bool CAUSAL_SKIP, bool KCAUSAL, bool TRANS_OUT, bool OUT_HALF>
__global__ __launch_bounds__(NTH)
void tg(const __half* __restrict__ A, const __half* __restrict__ Bm,
        const float* __restrict__ bias, void* __restrict__ Cv,
        int lda, int ldb, int ldc, int K,
        long strideA, long strideB, long strideC, float scale)
{
    extern __shared__ __half sm[];

    const int m0 = blockIdx.x * BM;
    const int n0 = blockIdx.y * BN;
    if (CAUSAL_SKIP && n0 > m0) return;

    const int bz = blockIdx.z;
    const __half* Ab = A  + (size_t)bz * strideA;
    const __half* Bb = Bm + (size_t)bz * strideB;

    const int kEnd = KCAUSAL ? (m0 + BM) : K;
    const int nk   = kEnd / BKH;

    const int tid  = threadIdx.x;
    const int warp = tid >> 5;
    const int wm   = warp >> 1;     // 0..3 -> 32 rows
    const int wn   = warp & 1;      // 0..1 -> 64 cols

    const unsigned smBase = (unsigned)__cvta_generic_to_shared(sm);

    wmma::fragment<wmma::accumulator, 16, 16, 16, float> acc[2][4];
    #pragma unroll
    for (int i = 0; i < 2; i++)
        #pragma unroll
        for (int j = 0; j < 4; j++)
            wmma::fill_fragment(acc[i][j], 0.0f);

    // one stage = A(128x64h) + B(128x64h); 2048 x 16B chunks, 8 per thread
    auto loadStage = [&](int st, int k0) {
        const unsigned base = smBase + (unsigned)(st * STAGE_HALVES) * 2u;
        #pragma unroll
        for (int i = 0; i < 4; i++) {
            const int ci = i * NTH + tid;          // 0..1023
            const int r = ci >> 3, c8 = (ci & 7) << 3;
            cpa16(base + (unsigned)(r * KP + c8) * 2u,
                  Ab + (size_t)(m0 + r) * lda + k0 + c8);
        }
        const unsigned baseB = base + (unsigned)(BM * KP) * 2u;
        #pragma unroll
        for (int i = 0; i < 4; i++) {
            const int ci = i * NTH + tid;
            const int r = ci >> 3, c8 = (ci & 7) << 3;
            cpa16(baseB + (unsigned)(r * KP + c8) * 2u,
                  Bb + (size_t)(n0 + r) * ldb + k0 + c8);
        }
        asm volatile("cp.async.commit_group;");
    };

    loadStage(0, 0);

    for (int kt = 0; kt < nk; kt++) {
        if (kt + 1 < nk) {
            loadStage((kt + 1) & 1, (kt + 1) * BKH);
            asm volatile("cp.async.wait_group 1;" ::: "memory");
        } else {
            asm volatile("cp.async.wait_group 0;" ::: "memory");
        }
        __syncthreads();

        const __half* a0 = sm + (kt & 1) * STAGE_HALVES;
        const __half* b0 = a0 + BM * KP;

        #pragma unroll
        for (int kk = 0; kk < BKH; kk += 16) {
            wmma::fragment<wmma::matrix_a, 16, 16, 16, __half, wmma::row_major> af[2];
            #pragma unroll
            for (int i = 0; i < 2; i++)
                wmma::load_matrix_sync(af[i], a0 + (wm * 32 + i * 16) * KP + kk, KP);
            wmma::fragment<wmma::matrix_b, 16, 16, 16, __half, wmma::col_major> bf[4];
            #pragma unroll
            for (int j = 0; j < 4; j++)
                wmma::load_matrix_sync(bf[j], b0 + (wn * 64 + j * 16) * KP + kk, KP);
            #pragma unroll
            for (int i = 0; i < 2; i++)
                #pragma unroll
                for (int j = 0; j < 4; j++)
                    wmma::mma_sync(acc[i][j], af[i], bf[j], acc[i][j]);
        }
        __syncthreads();
    }

    // ---- epilogue: fp32 stage in smem, then typed store ----
    float* sC = reinterpret_cast<float*>(sm);
    #pragma unroll
    for (int i = 0; i < 2; i++)
        #pragma unroll
        for (int j = 0; j < 4; j++)
            wmma::store_matrix_sync(sC + (wm * 32 + i * 16) * SC_LD + wn * 64 + j * 16,
                                    acc[i][j], SC_LD, wmma::mem_row_major);
    __syncthreads();

    if (TRANS_OUT) {
        // Vt[n][m] fp16; lanes walk m (coalesced 64B stores)
        __half* Cb = reinterpret_cast<__half*>(Cv) + (size_t)bz * strideC;
        const int lane = tid & 31;
        #pragma unroll
        for (int cc = 0; cc < 16; cc++) {
            const int c = warp * 16 + cc;
            const float bb = bias ? __ldg(bias + n0 + c) : 0.0f;
            #pragma unroll
            for (int r0 = 0; r0 < BM; r0 += 32) {
                float v = sC[(r0 + lane) * SC_LD + c] * scale + bb;
                Cb[(size_t)(n0 + c) * ldc + m0 + r0 + lane] = __float2half(v);
            }
        }
    } else {
        const int r  = tid >> 5;            // 0..7
        const int c4 = (tid & 31) << 2;     // 0..124
        float4 bb = make_float4(0.f, 0.f, 0.f, 0.f);
        if (bias) bb = *reinterpret_cast<const float4*>(bias + n0 + c4);
        #pragma unroll
        for (int rr = 0; rr < BM; rr += 8) {
            const int m = m0 + r + rr;
            float4 v = *reinterpret_cast<float4*>(&sC[(r + rr) * SC_LD + c4]);
            v.x = v.x * scale + bb.x;
            v.y = v.y * scale + bb.y;
            v.z = v.z * scale + bb.z;
            v.w = v.w * scale + bb.w;
            if (OUT_HALF) {
                __half2 h0 = __floats2half2_rn(v.x, v.y);
                __half2 h1 = __floats2half2_rn(v.z, v.w);
                __half2* dst = reinterpret_cast<__half2*>(
                    reinterpret_cast<__half*>(Cv) + (size_t)bz * strideC + (size_t)m * ldc + n0 + c4);
                dst[0] = h0; dst[1] = h1;
            } else {
                *reinterpret_cast<float4*>(
                    reinterpret_cast<float*>(Cv) + (size_t)bz * strideC + (size_t)m * ldc + n0 + c4) = v;
            }
        }
    }
}

// ---------------- fp32 -> fp16 convert ----------------
__global__ __launch_bounds__(256)
void f2h(const float* __restrict__ in, __half* __restrict__ out, int n4)
{
    int i = blockIdx.x * 256 + threadIdx.x;
    if (i < n4) {
        float4 v = reinterpret_cast<const float4*>(in)[i];
        __half2 h0 = __floats2half2_rn(v.x, v.y);
        __half2 h1 = __floats2half2_rn(v.z, v.w);
        reinterpret_cast<__half2*>(out)[2 * i + 0] = h0;
        reinterpret_cast<__half2*>(out)[2 * i + 1] = h1;
    }
}

// bout[e] = b[e] + dot(W[e,:], ctx)  (fp32, exact fold of context into bias)
__global__ __launch_bounds__(256)
void bias_prep(const float* __restrict__ W, const float* __restrict__ b,
               const float* __restrict__ ctx, float* __restrict__ bout)
{
    __shared__ float red[8];
    const int e = blockIdx.x;
    const int tid = threadIdx.x, lane = tid & 31, w = tid >> 5;
    float s = 0.f;
    for (int d = tid; d < DIM; d += 256) s += W[(size_t)e * DIM + d] * ctx[d];
    #pragma unroll
    for (int o = 16; o; o >>= 1) s += __shfl_xor_sync(0xffffffffu, s, o);
    if (lane == 0) red[w] = s;
    __syncthreads();
    if (tid == 0) {
        float t = 0.f;
        #pragma unroll
        for (int x = 0; x < 8; x++) t += red[x];
        bout[e] = b[e] + t;
    }
}

// Causal row softmax: fp32 scores in, fp16 probs out (zero-filled to 128 boundary)
__global__ __launch_bounds__(256)
void softmax_kernel(const float* __restrict__ S, __half* __restrict__ P)
{
    __shared__ float buf[SEQ];
    __shared__ float red[8];
    const int row = blockIdx.x;
    const int b   = row >> 11;
    const int i   = row & (SEQ - 1);
    const float* p = S + ((size_t)b * SEQ + i) * SEQ;
    __half* q = P + ((size_t)b * SEQ + i) * SEQ;
    const int len = i + 1;
    const int tid = threadIdx.x, lane = tid & 31, w = tid >> 5;

    float m = -1e30f;
    for (int j = tid; j < len; j += 256) { float v = p[j]; buf[j] = v; m = fmaxf(m, v); }
    #pragma unroll
    for (int o = 16; o; o >>= 1) m = fmaxf(m, __shfl_xor_sync(0xffffffffu, m, o));
    if (lane == 0) red[w] = m;
    __syncthreads();
    if (tid == 0) {
        float mm = red[0];
        #pragma unroll
        for (int x = 1; x < 8; x++) mm = fmaxf(mm, red[x]);
        red[0] = mm;
    }
    __syncthreads();
    m = red[0];
    __syncthreads();

    float s = 0.f;
    for (int j = tid; j < len; j += 256) { float e = __expf(buf[j] - m); buf[j] = e; s += e; }
    #pragma unroll
    for (int o = 16; o; o >>= 1) s += __shfl_xor_sync(0xffffffffu, s, o);
    if (lane == 0) red[w] = s;
    __syncthreads();
    if (tid == 0) {
        float ss = red[0];
        #pragma unroll
        for (int x = 1; x < 8; x++) ss += red[x];
        red[0] = ss;
    }
    __syncthreads();
    const float inv = 1.0f / red[0];

    const int zend = min(SEQ, ((i >> 7) + 1) << 7);
    for (int j = tid; j < zend; j += 256)
        q[j] = (j < len) ? __float2half(buf[j] * inv) : __float2half(0.0f);
}

extern "C" void kernel_launch(void* const* d_in, const int* in_sizes, int n_in,
                              void* d_out, int out_size)
{
    const float* query = (const float*)d_in[0];
    const float* key   = (const float*)d_in[1];
    const float* value = (const float*)d_in[2];
    const float* ctx   = (const float*)d_in[3];
    const float* Wq    = (const float*)d_in[4];
    const float* bq    = (const float*)d_in[5];
    const float* Wk    = (const float*)d_in[6];
    const float* bk    = (const float*)d_in[7];
    const float* Wv    = (const float*)d_in[8];
    const float* bv    = (const float*)d_in[9];
    float* out = (float*)d_out;

    float *pS, *pBias;
    __half *phP, *phQ, *phK, *phVt, *phX, *phW;
    cudaGetSymbolAddress((void**)&pS,  g_S);
    cudaGetSymbolAddress((void**)&phP, g_hP);
    cudaGetSymbolAddress((void**)&phQ, g_hQ);
    cudaGetSymbolAddress((void**)&phK, g_hK);
    cudaGetSymbolAddress((void**)&phVt, g_hVt);
    cudaGetSymbolAddress((void**)&phX, g_hX);
    cudaGetSymbolAddress((void**)&phW, g_hW);
    cudaGetSymbolAddress((void**)&pBias, g_bias);

    cudaFuncSetAttribute(tg<false, false, false, true >, cudaFuncAttributeMaxDynamicSharedMemorySize, SMEM_BYTES);
    cudaFuncSetAttribute(tg<false, false, true,  true >, cudaFuncAttributeMaxDynamicSharedMemorySize, SMEM_BYTES);
    cudaFuncSetAttribute(tg<true,  false, false, false>, cudaFuncAttributeMaxDynamicSharedMemorySize, SMEM_BYTES);
    cudaFuncSetAttribute(tg<false, true,  false, false>, cudaFuncAttributeMaxDynamicSharedMemorySize, SMEM_BYTES);

    const int nX4 = MTOT * DIM / 4;
    const int nW4 = DIM * DIM / 4;

    bias_prep<<<DIM, 256>>>(Wq, bq, ctx, pBias);
    bias_prep<<<DIM, 256>>>(Wk, bk, ctx, pBias + DIM);

    dim3 gp(MTOT / BM, DIM / BN, 1);

    // Q projection (fp16 out)
    f2h<<<nX4 / 256, 256>>>(query, phX, nX4);
    f2h<<<nW4 / 256, 256>>>(Wq, phW, nW4);
    tg<false, false, false, true><<<gp, NTH, SMEM_BYTES>>>(phX, phW, pBias, phQ,
        DIM, DIM, DIM, DIM, 0, 0, 0, 1.0f);

    // K projection
    f2h<<<nX4 / 256, 256>>>(key, phX, nX4);
    f2h<<<nW4 / 256, 256>>>(Wk, phW, nW4);
    tg<false, false, false, true><<<gp, NTH, SMEM_BYTES>>>(phX, phW, pBias + DIM, phK,
        DIM, DIM, DIM, DIM, 0, 0, 0, 1.0f);

    // V projection -> transposed fp16 Vt [DIM][MTOT]
    f2h<<<nX4 / 256, 256>>>(value, phX, nX4);
    f2h<<<nW4 / 256, 256>>>(Wv, phW, nW4);
    tg<false, false, true, true><<<gp, NTH, SMEM_BYTES>>>(phX, phW, bv, phVt,
        DIM, DIM, MTOT, DIM, 0, 0, 0, 1.0f);

    // scores = Q @ K^T * scale (causal block skip), fp32 out
    dim3 gs(SEQ / BM, SEQ / BN, BATCH);
    tg<true, false, false, false><<<gs, NTH, SMEM_BYTES>>>(phQ, phK, nullptr, pS,
        DIM, DIM, SEQ, DIM,
        (long)SEQ * DIM, (long)SEQ * DIM, (long)SEQ * SEQ, 0.03125f);

    // causal softmax: fp32 scores -> fp16 probs
    softmax_kernel<<<MTOT, 256>>>(pS, phP);

    // out = P @ Vt^T (K limited by causality), fp32 out
    dim3 gv(SEQ / BM, DIM / BN, BATCH);
    tg<false, true, false, false><<<gv, NTH, SMEM_BYTES>>>(phP, phVt, nullptr, out,
        SEQ, MTOT, DIM, SEQ,
        (long)SEQ * SEQ, (long)SEQ, (long)SEQ * DIM, 1.0f);
}

// round 6
// speedup vs baseline: 4.2000x; 1.0100x over previous
#include <cuda_runtime.h>
#include <cstdint>
#include <cuda_fp16.h>
#include <mma.h>

using namespace nvcuda;

#define DIM   1024
#define BATCH 8
#define SEQ   2048
#define MTOT  (BATCH*SEQ)   // 16384

#define BM 128
#define BN 128
#define BKH 64              // K halves per tile (128 bytes/row)
#define KP  72              // padded smem row (halves)
#define SC_LD 132           // epilogue fp32 staging ld
#define STAGE_HALVES (2*BM*KP)        // A + B per stage = 18432 halves
#define SMEM_BYTES (2*STAGE_HALVES*2) // 73728 B
#define NTH 128             // 4 warps: 2x2 grid of 64x64 warp tiles

// ---------------- scratch (__device__ globals; no allocation) ----------------
__device__ float  g_S [(size_t)BATCH * SEQ * SEQ];   // fp32 scores
__device__ __half g_hP[(size_t)BATCH * SEQ * SEQ];   // fp16 probs
__device__ __half g_hQ[(size_t)MTOT * DIM];
__device__ __half g_hK[(size_t)MTOT * DIM];
__device__ __half g_hVt[(size_t)DIM * MTOT];         // V projection TRANSPOSED
__device__ __half g_hX[(size_t)MTOT * DIM];          // staging: fp16 input
__device__ __half g_hW[(size_t)DIM * DIM];           // staging: fp16 weight
__device__ float  g_bias[2 * DIM];

__device__ __forceinline__ void cpa16(unsigned saddr, const void* gaddr) {
    asm volatile("cp.async.cg.shared.global [%0], [%1], 16;" :: "r"(saddr), "l"(gaddr));
}

// ---------------- fp16 tensor-core GEMM ----------------
// C(M,N) = A(M,K) * B(N,K)^T ; fp16 in, fp32 accumulate.
template<bool CAUSAL_SKIP, bool KCAUSAL, bool TRANS_OUT, bool OUT_HALF>
__global__ __launch_bounds__(NTH)
void tg(const __half* __restrict__ A, const __half* __restrict__ Bm,
        const float* __restrict__ bias, void* __restrict__ Cv,
        int lda, int ldb, int ldc, int K,
        long strideA, long strideB, long strideC, float scale)
{
    extern __shared__ __half sm[];

    const int m0 = blockIdx.x * BM;
    const int n0 = blockIdx.y * BN;
    if (CAUSAL_SKIP && n0 > m0) return;

    const int bz = blockIdx.z;
    const __half* Ab = A  + (size_t)bz * strideA;
    const __half* Bb = Bm + (size_t)bz * strideB;

    const int kEnd = KCAUSAL ? (m0 + BM) : K;
    const int nk   = kEnd / BKH;

    const int tid  = threadIdx.x;
    const int warp = tid >> 5;
    const int wm   = warp >> 1;     // 0..1 -> 64 rows
    const int wn   = warp & 1;      // 0..1 -> 64 cols

    const unsigned smBase = (unsigned)__cvta_generic_to_shared(sm);

    wmma::fragment<wmma::accumulator, 16, 16, 16, float> acc[4][4];
    #pragma unroll
    for (int i = 0; i < 4; i++)
        #pragma unroll
        for (int j = 0; j < 4; j++)
            wmma::fill_fragment(acc[i][j], 0.0f);

    // one stage = A(128x64h) + B(128x64h) = 2048 x 16B chunks; 16 per thread
    auto loadStage = [&](int st, int k0) {
        const unsigned base = smBase + (unsigned)(st * STAGE_HALVES) * 2u;
        #pragma unroll
        for (int i = 0; i < 8; i++) {
            const int ci = i * NTH + tid;          // 0..1023
            const int r = ci >> 3, c8 = (ci & 7) << 3;
            cpa16(base + (unsigned)(r * KP + c8) * 2u,
                  Ab + (size_t)(m0 + r) * lda + k0 + c8);
        }
        const unsigned baseB = base + (unsigned)(BM * KP) * 2u;
        #pragma unroll
        for (int i = 0; i < 8; i++) {
            const int ci = i * NTH + tid;
            const int r = ci >> 3, c8 = (ci & 7) << 3;
            cpa16(baseB + (unsigned)(r * KP + c8) * 2u,
                  Bb + (size_t)(n0 + r) * ldb + k0 + c8);
        }
        asm volatile("cp.async.commit_group;");
    };

    loadStage(0, 0);

    for (int kt = 0; kt < nk; kt++) {
        if (kt + 1 < nk) {
            loadStage((kt + 1) & 1, (kt + 1) * BKH);
            asm volatile("cp.async.wait_group 1;" ::: "memory");
        } else {
            asm volatile("cp.async.wait_group 0;" ::: "memory");
        }
        __syncthreads();

        const __half* a0 = sm + (kt & 1) * STAGE_HALVES;
        const __half* b0 = a0 + BM * KP;

        #pragma unroll
        for (int kk = 0; kk < BKH; kk += 16) {
            wmma::fragment<wmma::matrix_a, 16, 16, 16, __half, wmma::row_major> af[4];
            #pragma unroll
            for (int i = 0; i < 4; i++)
                wmma::load_matrix_sync(af[i], a0 + (wm * 64 + i * 16) * KP + kk, KP);
            #pragma unroll
            for (int j = 0; j < 4; j++) {
                wmma::fragment<wmma::matrix_b, 16, 16, 16, __half, wmma::col_major> bf;
                wmma::load_matrix_sync(bf, b0 + (wn * 64 + j * 16) * KP + kk, KP);
                #pragma unroll
                for (int i = 0; i < 4; i++)
                    wmma::mma_sync(acc[i][j], af[i], bf, acc[i][j]);
            }
        }
        __syncthreads();
    }

    // ---- epilogue: fp32 stage in smem, then typed store ----
    float* sC = reinterpret_cast<float*>(sm);
    #pragma unroll
    for (int i = 0; i < 4; i++)
        #pragma unroll
        for (int j = 0; j < 4; j++)
            wmma::store_matrix_sync(sC + (wm * 64 + i * 16) * SC_LD + wn * 64 + j * 16,
                                    acc[i][j], SC_LD, wmma::mem_row_major);
    __syncthreads();

    if (TRANS_OUT) {
        // Vt[n][m] fp16; warp owns 32 cols, lanes walk m (coalesced)
        __half* Cb = reinterpret_cast<__half*>(Cv) + (size_t)bz * strideC;
        const int lane = tid & 31;
        #pragma unroll
        for (int cc = 0; cc < 32; cc++) {
            const int c = warp * 32 + cc;
            const float bb = bias ? __ldg(bias + n0 + c) : 0.0f;
            #pragma unroll
            for (int r0 = 0; r0 < BM; r0 += 32) {
                float v = sC[(r0 + lane) * SC_LD + c] * scale + bb;
                Cb[(size_t)(n0 + c) * ldc + m0 + r0 + lane] = __float2half(v);
            }
        }
    } else {
        const int r  = tid >> 5;            // 0..3
        const int c4 = (tid & 31) << 2;     // 0..124
        float4 bb = make_float4(0.f, 0.f, 0.f, 0.f);
        if (bias) bb = *reinterpret_cast<const float4*>(bias + n0 + c4);
        #pragma unroll
        for (int rr = 0; rr < BM; rr += 4) {
            const int m = m0 + r + rr;
            float4 v = *reinterpret_cast<float4*>(&sC[(r + rr) * SC_LD + c4]);
            v.x = v.x * scale + bb.x;
            v.y = v.y * scale + bb.y;
            v.z = v.z * scale + bb.z;
            v.w = v.w * scale + bb.w;
            if (OUT_HALF) {
                __half2 h0 = __floats2half2_rn(v.x, v.y);
                __half2 h1 = __floats2half2_rn(v.z, v.w);
                __half2* dst = reinterpret_cast<__half2*>(
                    reinterpret_cast<__half*>(Cv) + (size_t)bz * strideC + (size_t)m * ldc + n0 + c4);
                dst[0] = h0; dst[1] = h1;
            } else {
                *reinterpret_cast<float4*>(
                    reinterpret_cast<float*>(Cv) + (size_t)bz * strideC + (size_t)m * ldc + n0 + c4) = v;
            }
        }
    }
}

// ---------------- fp32 -> fp16 convert ----------------
__global__ __launch_bounds__(256)
void f2h(const float* __restrict__ in, __half* __restrict__ out, int n4)
{
    int i = blockIdx.x * 256 + threadIdx.x;
    if (i < n4) {
        float4 v = reinterpret_cast<const float4*>(in)[i];
        __half2 h0 = __floats2half2_rn(v.x, v.y);
        __half2 h1 = __floats2half2_rn(v.z, v.w);
        reinterpret_cast<__half2*>(out)[2 * i + 0] = h0;
        reinterpret_cast<__half2*>(out)[2 * i + 1] = h1;
    }
}

// bout[e] = b[e] + dot(W[e,:], ctx)
__global__ __launch_bounds__(256)
void bias_prep(const float* __restrict__ W, const float* __restrict__ b,
               const float* __restrict__ ctx, float* __restrict__ bout)
{
    __shared__ float red[8];
    const int e = blockIdx.x;
    const int tid = threadIdx.x, lane = tid & 31, w = tid >> 5;
    float s = 0.f;
    for (int d = tid; d < DIM; d += 256) s += W[(size_t)e * DIM + d] * ctx[d];
    #pragma unroll
    for (int o = 16; o; o >>= 1) s += __shfl_xor_sync(0xffffffffu, s, o);
    if (lane == 0) red[w] = s;
    __syncthreads();
    if (tid == 0) {
        float t = 0.f;
        #pragma unroll
        for (int x = 0; x < 8; x++) t += red[x];
        bout[e] = b[e] + t;
    }
}

// Causal row softmax: fp32 scores in, fp16 probs out (zero-filled to 128 boundary)
__global__ __launch_bounds__(256)
void softmax_kernel(const float* __restrict__ S, __half* __restrict__ P)
{
    __shared__ float buf[SEQ];
    __shared__ float red[8];
    const int row = blockIdx.x;
    const int b   = row >> 11;
    const int i   = row & (SEQ - 1);
    const float* p = S + ((size_t)b * SEQ + i) * SEQ;
    __half* q = P + ((size_t)b * SEQ + i) * SEQ;
    const int len = i + 1;
    const int tid = threadIdx.x, lane = tid & 31, w = tid >> 5;

    float m = -1e30f;
    for (int j = tid; j < len; j += 256) { float v = p[j]; buf[j] = v; m = fmaxf(m, v); }
    #pragma unroll
    for (int o = 16; o; o >>= 1) m = fmaxf(m, __shfl_xor_sync(0xffffffffu, m, o));
    if (lane == 0) red[w] = m;
    __syncthreads();
    if (tid == 0) {
        float mm = red[0];
        #pragma unroll
        for (int x = 1; x < 8; x++) mm = fmaxf(mm, red[x]);
        red[0] = mm;
    }
    __syncthreads();
    m = red[0];
    __syncthreads();

    float s = 0.f;
    for (int j = tid; j < len; j += 256) { float e = __expf(buf[j] - m); buf[j] = e; s += e; }
    #pragma unroll
    for (int o = 16; o; o >>= 1) s += __shfl_xor_sync(0xffffffffu, s, o);
    if (lane == 0) red[w] = s;
    __syncthreads();
    if (tid == 0) {
        float ss = red[0];
        #pragma unroll
        for (int x = 1; x < 8; x++) ss += red[x];
        red[0] = ss;
    }
    __syncthreads();
    const float inv = 1.0f / red[0];

    const int zend = min(SEQ, ((i >> 7) + 1) << 7);
    for (int j = tid; j < zend; j += 256)
        q[j] = (j < len) ? __float2half(buf[j] * inv) : __float2half(0.0f);
}

extern "C" void kernel_launch(void* const* d_in, const int* in_sizes, int n_in,
                              void* d_out, int out_size)
{
    const float* query = (const float*)d_in[0];
    const float* key   = (const float*)d_in[1];
    const float* value = (const float*)d_in[2];
    const float* ctx   = (const float*)d_in[3];
    const float* Wq    = (const float*)d_in[4];
    const float* bq    = (const float*)d_in[5];
    const float* Wk    = (const float*)d_in[6];
    const float* bk    = (const float*)d_in[7];
    const float* Wv    = (const float*)d_in[8];
    const float* bv    = (const float*)d_in[9];
    float* out = (float*)d_out;

    float *pS, *pBias;
    __half *phP, *phQ, *phK, *phVt, *phX, *phW;
    cudaGetSymbolAddress((void**)&pS,  g_S);
    cudaGetSymbolAddress((void**)&phP, g_hP);
    cudaGetSymbolAddress((void**)&phQ, g_hQ);
    cudaGetSymbolAddress((void**)&phK, g_hK);
    cudaGetSymbolAddress((void**)&phVt, g_hVt);
    cudaGetSymbolAddress((void**)&phX, g_hX);
    cudaGetSymbolAddress((void**)&phW, g_hW);
    cudaGetSymbolAddress((void**)&pBias, g_bias);

    cudaFuncSetAttribute(tg<false, false, false, true >, cudaFuncAttributeMaxDynamicSharedMemorySize, SMEM_BYTES);
    cudaFuncSetAttribute(tg<false, false, true,  true >, cudaFuncAttributeMaxDynamicSharedMemorySize, SMEM_BYTES);
    cudaFuncSetAttribute(tg<true,  false, false, false>, cudaFuncAttributeMaxDynamicSharedMemorySize, SMEM_BYTES);
    cudaFuncSetAttribute(tg<false, true,  false, false>, cudaFuncAttributeMaxDynamicSharedMemorySize, SMEM_BYTES);

    const int nX4 = MTOT * DIM / 4;
    const int nW4 = DIM * DIM / 4;

    bias_prep<<<DIM, 256>>>(Wq, bq, ctx, pBias);
    bias_prep<<<DIM, 256>>>(Wk, bk, ctx, pBias + DIM);

    dim3 gp(MTOT / BM, DIM / BN, 1);

    // Q projection (fp16 out)
    f2h<<<nX4 / 256, 256>>>(query, phX, nX4);
    f2h<<<nW4 / 256, 256>>>(Wq, phW, nW4);
    tg<false, false, false, true><<<gp, NTH, SMEM_BYTES>>>(phX, phW, pBias, phQ,
        DIM, DIM, DIM, DIM, 0, 0, 0, 1.0f);

    // K projection
    f2h<<<nX4 / 256, 256>>>(key, phX, nX4);
    f2h<<<nW4 / 256, 256>>>(Wk, phW, nW4);
    tg<false, false, false, true><<<gp, NTH, SMEM_BYTES>>>(phX, phW, pBias + DIM, phK,
        DIM, DIM, DIM, DIM, 0, 0, 0, 1.0f);

    // V projection -> transposed fp16 Vt [DIM][MTOT]
    f2h<<<nX4 / 256, 256>>>(value, phX, nX4);
    f2h<<<nW4 / 256, 256>>>(Wv, phW, nW4);
    tg<false, false, true, true><<<gp, NTH, SMEM_BYTES>>>(phX, phW, bv, phVt,
        DIM, DIM, MTOT, DIM, 0, 0, 0, 1.0f);

    // scores = Q @ K^T * scale (causal block skip), fp32 out
    dim3 gs(SEQ / BM, SEQ / BN, BATCH);
    tg<true, false, false, false><<<gs, NTH, SMEM_BYTES>>>(phQ, phK, nullptr, pS,
        DIM, DIM, SEQ, DIM,
        (long)SEQ * DIM, (long)SEQ * DIM, (long)SEQ * SEQ, 0.03125f);

    // causal softmax: fp32 scores -> fp16 probs
    softmax_kernel<<<MTOT, 256>>>(pS, phP);

    // out = P @ Vt^T (K limited by causality), fp32 out
    dim3 gv(SEQ / BM, DIM / BN, BATCH);
    tg<false, true, false, false><<<gv, NTH, SMEM_BYTES>>>(phP, phVt, nullptr, out,
        SEQ, MTOT, DIM, SEQ,
        (long)SEQ * SEQ, (long)SEQ, (long)SEQ * DIM, 1.0f);
}

// round 7
// speedup vs baseline: 4.2545x; 1.0130x over previous
#include <cuda_runtime.h>
#include <cstdint>
#include <cuda_fp16.h>
#include <mma.h>

using namespace nvcuda;

#define DIM   1024
#define BATCH 8
#define SEQ   2048
#define MTOT  (BATCH*SEQ)   // 16384

#define BM 128
#define BN 128
#define BKH 64              // K halves per tile (128 bytes/row)
#define KP  72              // padded smem row (halves)
#define SC_LD 132           // epilogue fp32 staging ld
#define STAGE_HALVES (2*BM*KP)        // A + B per stage = 18432 halves
#define SMEM_BYTES (2*STAGE_HALVES*2) // 73728 B
#define NTH 128             // 4 warps: 2x2 grid of 64x64 warp tiles

// ---------------- scratch (__device__ globals; no allocation) ----------------
__device__ float  g_S [(size_t)BATCH * SEQ * SEQ];   // fp32 scores
__device__ __half g_hP[(size_t)BATCH * SEQ * SEQ];   // fp16 probs
__device__ __half g_hQ [(size_t)MTOT * DIM];
__device__ __half g_hK [(size_t)MTOT * DIM];
__device__ __half g_hVt[(size_t)DIM * MTOT];         // V projection TRANSPOSED
__device__ __half g_hXq[(size_t)MTOT * DIM];         // fp16 staging per projection
__device__ __half g_hXk[(size_t)MTOT * DIM];
__device__ __half g_hXv[(size_t)MTOT * DIM];
__device__ __half g_hWq[(size_t)DIM * DIM];
__device__ __half g_hWk[(size_t)DIM * DIM];
__device__ __half g_hWv[(size_t)DIM * DIM];
__device__ float  g_bias[2 * DIM];

__device__ __forceinline__ void cpa16(unsigned saddr, const void* gaddr) {
    asm volatile("cp.async.cg.shared.global [%0], [%1], 16;" :: "r"(saddr), "l"(gaddr));
}

// ---------------- fp16 tensor-core GEMM ----------------
// C(M,N) = A(M,K) * B(N,K)^T ; fp16 in, fp32 accumulate.
template<bool CAUSAL_SKIP, bool KCAUSAL, bool TRANS_OUT, bool OUT_HALF>
__global__ __launch_bounds__(NTH)
void tg(const __half* __restrict__ A, const __half* __restrict__ Bm,
        const float* __restrict__ bias, void* __restrict__ Cv,
        int lda, int ldb, int ldc, int K,
        long strideA, long strideB, long strideC, float scale)
{
    extern __shared__ __half sm[];

    const int m0 = blockIdx.x * BM;
    const int n0 = blockIdx.y * BN;
    if (CAUSAL_SKIP && n0 > m0) return;

    const int bz = blockIdx.z;
    const __half* Ab = A  + (size_t)bz * strideA;
    const __half* Bb = Bm + (size_t)bz * strideB;

    const int kEnd = KCAUSAL ? (m0 + BM) : K;
    const int nk   = kEnd / BKH;

    const int tid  = threadIdx.x;
    const int warp = tid >> 5;
    const int wm   = warp >> 1;     // 0..1 -> 64 rows
    const int wn   = warp & 1;      // 0..1 -> 64 cols

    const unsigned smBase = (unsigned)__cvta_generic_to_shared(sm);

    wmma::fragment<wmma::accumulator, 16, 16, 16, float> acc[4][4];
    #pragma unroll
    for (int i = 0; i < 4; i++)
        #pragma unroll
        for (int j = 0; j < 4; j++)
            wmma::fill_fragment(acc[i][j], 0.0f);

    auto loadStage = [&](int st, int k0) {
        const unsigned base = smBase + (unsigned)(st * STAGE_HALVES) * 2u;
        #pragma unroll
        for (int i = 0; i < 8; i++) {
            const int ci = i * NTH + tid;
            const int r = ci >> 3, c8 = (ci & 7) << 3;
            cpa16(base + (unsigned)(r * KP + c8) * 2u,
                  Ab + (size_t)(m0 + r) * lda + k0 + c8);
        }
        const unsigned baseB = base + (unsigned)(BM * KP) * 2u;
        #pragma unroll
        for (int i = 0; i < 8; i++) {
            const int ci = i * NTH + tid;
            const int r = ci >> 3, c8 = (ci & 7) << 3;
            cpa16(baseB + (unsigned)(r * KP + c8) * 2u,
                  Bb + (size_t)(n0 + r) * ldb + k0 + c8);
        }
        asm volatile("cp.async.commit_group;");
    };

    loadStage(0, 0);

    for (int kt = 0; kt < nk; kt++) {
        if (kt + 1 < nk) {
            loadStage((kt + 1) & 1, (kt + 1) * BKH);
            asm volatile("cp.async.wait_group 1;" ::: "memory");
        } else {
            asm volatile("cp.async.wait_group 0;" ::: "memory");
        }
        __syncthreads();

        const __half* a0 = sm + (kt & 1) * STAGE_HALVES;
        const __half* b0 = a0 + BM * KP;

        #pragma unroll
        for (int kk = 0; kk < BKH; kk += 16) {
            wmma::fragment<wmma::matrix_a, 16, 16, 16, __half, wmma::row_major> af[4];
            #pragma unroll
            for (int i = 0; i < 4; i++)
                wmma::load_matrix_sync(af[i], a0 + (wm * 64 + i * 16) * KP + kk, KP);
            #pragma unroll
            for (int j = 0; j < 4; j++) {
                wmma::fragment<wmma::matrix_b, 16, 16, 16, __half, wmma::col_major> bf;
                wmma::load_matrix_sync(bf, b0 + (wn * 64 + j * 16) * KP + kk, KP);
                #pragma unroll
                for (int i = 0; i < 4; i++)
                    wmma::mma_sync(acc[i][j], af[i], bf, acc[i][j]);
            }
        }
        __syncthreads();
    }

    // ---- epilogue ----
    float* sC = reinterpret_cast<float*>(sm);
    #pragma unroll
    for (int i = 0; i < 4; i++)
        #pragma unroll
        for (int j = 0; j < 4; j++)
            wmma::store_matrix_sync(sC + (wm * 64 + i * 16) * SC_LD + wn * 64 + j * 16,
                                    acc[i][j], SC_LD, wmma::mem_row_major);
    __syncthreads();

    if (TRANS_OUT) {
        __half* Cb = reinterpret_cast<__half*>(Cv) + (size_t)bz * strideC;
        const int lane = tid & 31;
        #pragma unroll
        for (int cc = 0; cc < 32; cc++) {
            const int c = warp * 32 + cc;
            const float bb = bias ? __ldg(bias + n0 + c) : 0.0f;
            #pragma unroll
            for (int r0 = 0; r0 < BM; r0 += 32) {
                float v = sC[(r0 + lane) * SC_LD + c] * scale + bb;
                Cb[(size_t)(n0 + c) * ldc + m0 + r0 + lane] = __float2half(v);
            }
        }
    } else {
        const int r  = tid >> 5;
        const int c4 = (tid & 31) << 2;
        float4 bb = make_float4(0.f, 0.f, 0.f, 0.f);
        if (bias) bb = *reinterpret_cast<const float4*>(bias + n0 + c4);
        #pragma unroll
        for (int rr = 0; rr < BM; rr += 4) {
            const int m = m0 + r + rr;
            float4 v = *reinterpret_cast<float4*>(&sC[(r + rr) * SC_LD + c4]);
            v.x = v.x * scale + bb.x;
            v.y = v.y * scale + bb.y;
            v.z = v.z * scale + bb.z;
            v.w = v.w * scale + bb.w;
            if (OUT_HALF) {
                __half2 h0 = __floats2half2_rn(v.x, v.y);
                __half2 h1 = __floats2half2_rn(v.z, v.w);
                __half2* dst = reinterpret_cast<__half2*>(
                    reinterpret_cast<__half*>(Cv) + (size_t)bz * strideC + (size_t)m * ldc + n0 + c4);
                dst[0] = h0; dst[1] = h1;
            } else {
                *reinterpret_cast<float4*>(
                    reinterpret_cast<float*>(Cv) + (size_t)bz * strideC + (size_t)m * ldc + n0 + c4) = v;
            }
        }
    }
}

// ---------------- fp32 -> fp16 convert ----------------
__global__ __launch_bounds__(256)
void f2h(const float* __restrict__ in, __half* __restrict__ out, int n4)
{
    int i = blockIdx.x * 256 + threadIdx.x;
    if (i < n4) {
        float4 v = reinterpret_cast<const float4*>(in)[i];
        __half2 h0 = __floats2half2_rn(v.x, v.y);
        __half2 h1 = __floats2half2_rn(v.z, v.w);
        reinterpret_cast<__half2*>(out)[2 * i + 0] = h0;
        reinterpret_cast<__half2*>(out)[2 * i + 1] = h1;
    }
}

// bout[e] = b[e] + dot(W[e,:], ctx)
__global__ __launch_bounds__(256)
void bias_prep(const float* __restrict__ W, const float* __restrict__ b,
               const float* __restrict__ ctx, float* __restrict__ bout)
{
    __shared__ float red[8];
    const int e = blockIdx.x;
    const int tid = threadIdx.x, lane = tid & 31, w = tid >> 5;
    float s = 0.f;
    for (int d = tid; d < DIM; d += 256) s += W[(size_t)e * DIM + d] * ctx[d];
    #pragma unroll
    for (int o = 16; o; o >>= 1) s += __shfl_xor_sync(0xffffffffu, s, o);
    if (lane == 0) red[w] = s;
    __syncthreads();
    if (tid == 0) {
        float t = 0.f;
        #pragma unroll
        for (int x = 0; x < 8; x++) t += red[x];
        bout[e] = b[e] + t;
    }
}

// Causal row softmax: fp32 scores in, fp16 probs out (zero-filled to 128 boundary)
__global__ __launch_bounds__(256)
void softmax_kernel(const float* __restrict__ S, __half* __restrict__ P)
{
    __shared__ float buf[SEQ];
    __shared__ float red[8];
    const int row = blockIdx.x;
    const int b   = row >> 11;
    const int i   = row & (SEQ - 1);
    const float* p = S + ((size_t)b * SEQ + i) * SEQ;
    __half* q = P + ((size_t)b * SEQ + i) * SEQ;
    const int len = i + 1;
    const int tid = threadIdx.x, lane = tid & 31, w = tid >> 5;

    float m = -1e30f;
    for (int j = tid; j < len; j += 256) { float v = p[j]; buf[j] = v; m = fmaxf(m, v); }
    #pragma unroll
    for (int o = 16; o; o >>= 1) m = fmaxf(m, __shfl_xor_sync(0xffffffffu, m, o));
    if (lane == 0) red[w] = m;
    __syncthreads();
    if (tid == 0) {
        float mm = red[0];
        #pragma unroll
        for (int x = 1; x < 8; x++) mm = fmaxf(mm, red[x]);
        red[0] = mm;
    }
    __syncthreads();
    m = red[0];
    __syncthreads();

    float s = 0.f;
    for (int j = tid; j < len; j += 256) { float e = __expf(buf[j] - m); buf[j] = e; s += e; }
    #pragma unroll
    for (int o = 16; o; o >>= 1) s += __shfl_xor_sync(0xffffffffu, s, o);
    if (lane == 0) red[w] = s;
    __syncthreads();
    if (tid == 0) {
        float ss = red[0];
        #pragma unroll
        for (int x = 1; x < 8; x++) ss += red[x];
        red[0] = ss;
    }
    __syncthreads();
    const float inv = 1.0f / red[0];

    const int zend = min(SEQ, ((i >> 7) + 1) << 7);
    for (int j = tid; j < zend; j += 256)
        q[j] = (j < len) ? __float2half(buf[j] * inv) : __float2half(0.0f);
}

extern "C" void kernel_launch(void* const* d_in, const int* in_sizes, int n_in,
                              void* d_out, int out_size)
{
    const float* query = (const float*)d_in[0];
    const float* key   = (const float*)d_in[1];
    const float* value = (const float*)d_in[2];
    const float* ctx   = (const float*)d_in[3];
    const float* Wq    = (const float*)d_in[4];
    const float* bq    = (const float*)d_in[5];
    const float* Wk    = (const float*)d_in[6];
    const float* bk    = (const float*)d_in[7];
    const float* Wv    = (const float*)d_in[8];
    const float* bv    = (const float*)d_in[9];
    float* out = (float*)d_out;

    float *pS, *pBias;
    __half *phP, *phQ, *phK, *phVt, *phXq, *phXk, *phXv, *phWq, *phWk, *phWv;
    cudaGetSymbolAddress((void**)&pS,   g_S);
    cudaGetSymbolAddress((void**)&phP,  g_hP);
    cudaGetSymbolAddress((void**)&phQ,  g_hQ);
    cudaGetSymbolAddress((void**)&phK,  g_hK);
    cudaGetSymbolAddress((void**)&phVt, g_hVt);
    cudaGetSymbolAddress((void**)&phXq, g_hXq);
    cudaGetSymbolAddress((void**)&phXk, g_hXk);
    cudaGetSymbolAddress((void**)&phXv, g_hXv);
    cudaGetSymbolAddress((void**)&phWq, g_hWq);
    cudaGetSymbolAddress((void**)&phWk, g_hWk);
    cudaGetSymbolAddress((void**)&phWv, g_hWv);
    cudaGetSymbolAddress((void**)&pBias, g_bias);

    cudaFuncSetAttribute(tg<false, false, false, true >, cudaFuncAttributeMaxDynamicSharedMemorySize, SMEM_BYTES);
    cudaFuncSetAttribute(tg<false, false, true,  true >, cudaFuncAttributeMaxDynamicSharedMemorySize, SMEM_BYTES);
    cudaFuncSetAttribute(tg<true,  false, false, false>, cudaFuncAttributeMaxDynamicSharedMemorySize, SMEM_BYTES);
    cudaFuncSetAttribute(tg<false, true,  false, false>, cudaFuncAttributeMaxDynamicSharedMemorySize, SMEM_BYTES);

    const int nX4 = MTOT * DIM / 4;
    const int nW4 = DIM * DIM / 4;

    // ---- fork an aux stream off the capture (legacy) stream ----
    cudaStream_t s1 = 0;
    cudaEvent_t evFork = 0, evJoin = 0;
    bool forked = false;
    if (cudaStreamCreateWithFlags(&s1, cudaStreamNonBlocking) == cudaSuccess) {
        cudaEventCreateWithFlags(&evFork, cudaEventDisableTiming);
        cudaEventCreateWithFlags(&evJoin, cudaEventDisableTiming);
        forked = (cudaEventRecord(evFork, 0) == cudaSuccess) &&
                 (cudaStreamWaitEvent(s1, evFork, 0) == cudaSuccess);
    }
    cudaStream_t sAux = forked ? s1 : 0;

    // aux stream: convert K/V inputs + all weights (memory-bound, overlaps GEMM_Q)
    f2h<<<nX4 / 256, 256, 0, sAux>>>(key,   phXk, nX4);
    f2h<<<nW4 / 256, 256, 0, sAux>>>(Wk,    phWk, nW4);
    f2h<<<nX4 / 256, 256, 0, sAux>>>(value, phXv, nX4);
    f2h<<<nW4 / 256, 256, 0, sAux>>>(Wv,    phWv, nW4);
    if (forked) cudaEventRecord(evJoin, sAux);

    // main stream: Q path
    bias_prep<<<DIM, 256>>>(Wq, bq, ctx, pBias);
    bias_prep<<<DIM, 256>>>(Wk, bk, ctx, pBias + DIM);
    f2h<<<nX4 / 256, 256>>>(query, phXq, nX4);
    f2h<<<nW4 / 256, 256>>>(Wq, phWq, nW4);

    dim3 gp(MTOT / BM, DIM / BN, 1);
    tg<false, false, false, true><<<gp, NTH, SMEM_BYTES>>>(phXq, phWq, pBias, phQ,
        DIM, DIM, DIM, DIM, 0, 0, 0, 1.0f);

    // join: K/V staging must be ready
    if (forked) cudaStreamWaitEvent(0, evJoin, 0);

    tg<false, false, false, true><<<gp, NTH, SMEM_BYTES>>>(phXk, phWk, pBias + DIM, phK,
        DIM, DIM, DIM, DIM, 0, 0, 0, 1.0f);

    tg<false, false, true, true><<<gp, NTH, SMEM_BYTES>>>(phXv, phWv, bv, phVt,
        DIM, DIM, MTOT, DIM, 0, 0, 0, 1.0f);

    // scores = Q @ K^T * scale (causal block skip)
    dim3 gs(SEQ / BM, SEQ / BN, BATCH);
    tg<true, false, false, false><<<gs, NTH, SMEM_BYTES>>>(phQ, phK, nullptr, pS,
        DIM, DIM, SEQ, DIM,
        (long)SEQ * DIM, (long)SEQ * DIM, (long)SEQ * SEQ, 0.03125f);

    // causal softmax: fp32 scores -> fp16 probs
    softmax_kernel<<<MTOT, 256>>>(pS, phP);

    // out = P @ Vt^T (K limited by causality)
    dim3 gv(SEQ / BM, DIM / BN, BATCH);
    tg<false, true, false, false><<<gv, NTH, SMEM_BYTES>>>(phP, phVt, nullptr, out,
        SEQ, MTOT, DIM, SEQ,
        (long)SEQ * SEQ, (long)SEQ, (long)SEQ * DIM, 1.0f);

    // cleanup host-side handles (deferred-safe; not device memory)
    if (forked) {
        cudaEventDestroy(evFork);
        cudaEventDestroy(evJoin);
    }
    if (s1) cudaStreamDestroy(s1);
}

// round 8
// speedup vs baseline: 4.3589x; 1.0245x over previous
#include <cuda_runtime.h>
#include <cstdint>
#include <cuda_fp16.h>
#include <mma.h>

using namespace nvcuda;

#define DIM   1024
#define BATCH 8
#define SEQ   2048
#define MTOT  (BATCH*SEQ)   // 16384

// ---- old-style fp16 GEMM (scores, PV) ----
#define BM 128
#define BN 128
#define BKH 64
#define KP  72
#define SC_LD 132
#define STAGE_HALVES (2*BM*KP)
#define SMEM_BYTES (2*STAGE_HALVES*2)  // 73728
#define NTH 128

// ---- projection GEMM (fp32 A inline-converted) ----
#define PKP 40                          // padded row halves (80B, 16B-multiple)
#define PST 5120                        // halves per A/B stage tile (128*40)
#define PSMEM_BYTES (4*PST*2)           // 40960

// ---------------- scratch ----------------
__device__ float  g_S [(size_t)BATCH * SEQ * SEQ];
__device__ __half g_hP[(size_t)BATCH * SEQ * SEQ];
__device__ __half g_hQ [(size_t)MTOT * DIM];
__device__ __half g_hK [(size_t)MTOT * DIM];
__device__ __half g_hVt[(size_t)DIM * MTOT];
__device__ __half g_hWq[(size_t)DIM * DIM];
__device__ __half g_hWk[(size_t)DIM * DIM];
__device__ __half g_hWv[(size_t)DIM * DIM];
__device__ float  g_bias[2 * DIM];

__device__ __forceinline__ void cpa16(unsigned saddr, const void* gaddr) {
    asm volatile("cp.async.cg.shared.global [%0], [%1], 16;" :: "r"(saddr), "l"(gaddr));
}

// ---------------- projection GEMM ----------------
// C(M,N) = A(M,K)*B(N,K)^T + bias; A fp32 (converted in-kernel), B fp16, C fp16.
// M tiles via blockIdx.x, N via blockIdx.y; K = DIM, lda = ldb = DIM.
template<bool TRANS_OUT>
__global__ __launch_bounds__(256, 2)
void ptg(const float* __restrict__ A, const __half* __restrict__ Bm,
         const float* __restrict__ bias, __half* __restrict__ C, int ldc)
{
    extern __shared__ __half sm[];
    const int m0 = blockIdx.x * 128;
    const int n0 = blockIdx.y * 128;
    const int tid = threadIdx.x, warp = tid >> 5, lane = tid & 31;
    const int wm = warp >> 1, wn = warp & 1;   // 32-row x 64-col warp tile
    const unsigned smBase = (unsigned)__cvta_generic_to_shared(sm);

    const int arr = tid >> 3;          // 0..31
    const int ac4 = (tid & 7) << 2;    // 0,4,..,28

    float4 areg[4];
    auto ldgA = [&](int k0) {
        #pragma unroll
        for (int i = 0; i < 4; i++)
            areg[i] = *reinterpret_cast<const float4*>(
                A + (size_t)(m0 + i * 32 + arr) * DIM + k0 + ac4);
    };
    auto stsA = [&](int st) {
        __half* dst0 = sm + st * PST;
        #pragma unroll
        for (int i = 0; i < 4; i++) {
            __half2 h01 = __floats2half2_rn(areg[i].x, areg[i].y);
            __half2 h23 = __floats2half2_rn(areg[i].z, areg[i].w);
            uint2 u;
            u.x = *reinterpret_cast<unsigned*>(&h01);
            u.y = *reinterpret_cast<unsigned*>(&h23);
            *reinterpret_cast<uint2*>(dst0 + (i * 32 + arr) * PKP + ac4) = u;
        }
    };
    auto ldB = [&](int st, int k0) {
        const unsigned dB = smBase + (unsigned)(2 * PST + st * PST) * 2u;
        #pragma unroll
        for (int i = 0; i < 2; i++) {
            const int r = i * 64 + (tid >> 2), c8 = (tid & 3) << 3;
            cpa16(dB + (unsigned)(r * PKP + c8) * 2u,
                  Bm + (size_t)(n0 + r) * DIM + k0 + c8);
        }
        asm volatile("cp.async.commit_group;");
    };

    wmma::fragment<wmma::accumulator, 16, 16, 16, float> acc[2][4];
    #pragma unroll
    for (int i = 0; i < 2; i++)
        #pragma unroll
        for (int j = 0; j < 4; j++)
            wmma::fill_fragment(acc[i][j], 0.0f);

    ldgA(0);
    ldB(0, 0);

    const int nk = DIM / 32;   // 32
    for (int kt = 0; kt < nk; kt++) {
        const int b = kt & 1;
        stsA(b);
        if (kt + 1 < nk) {
            ldgA((kt + 1) * 32);
            ldB(b ^ 1, (kt + 1) * 32);
            asm volatile("cp.async.wait_group 1;" ::: "memory");
        } else {
            asm volatile("cp.async.wait_group 0;" ::: "memory");
        }
        __syncthreads();

        const __half* a0 = sm + b * PST;
        const __half* b0 = sm + 2 * PST + b * PST;
        #pragma unroll
        for (int kk = 0; kk < 32; kk += 16) {
            wmma::fragment<wmma::matrix_a, 16, 16, 16, __half, wmma::row_major> af[2];
            #pragma unroll
            for (int i = 0; i < 2; i++)
                wmma::load_matrix_sync(af[i], a0 + (wm * 32 + i * 16) * PKP + kk, PKP);
            #pragma unroll
            for (int j = 0; j < 4; j++) {
                wmma::fragment<wmma::matrix_b, 16, 16, 16, __half, wmma::col_major> bf;
                wmma::load_matrix_sync(bf, b0 + (wn * 64 + j * 16) * PKP + kk, PKP);
                #pragma unroll
                for (int i = 0; i < 2; i++)
                    wmma::mma_sync(acc[i][j], af[i], bf, acc[i][j]);
            }
        }
        __syncthreads();
    }

    // ---- epilogue: two 64-row passes through 40KB smem ----
    float* sC = reinterpret_cast<float*>(sm);
    #pragma unroll
    for (int pass = 0; pass < 2; pass++) {
        if (pass) __syncthreads();
        if ((wm >> 1) == pass) {
            #pragma unroll
            for (int i = 0; i < 2; i++)
                #pragma unroll
                for (int j = 0; j < 4; j++)
                    wmma::store_matrix_sync(sC + ((wm & 1) * 32 + i * 16) * SC_LD + wn * 64 + j * 16,
                                            acc[i][j], SC_LD, wmma::mem_row_major);
        }
        __syncthreads();

        if (TRANS_OUT) {
            #pragma unroll
            for (int cc = 0; cc < 16; cc++) {
                const int c = warp * 16 + cc;
                const float bb = __ldg(bias + n0 + c);
                #pragma unroll
                for (int r0 = 0; r0 < 64; r0 += 32) {
                    float v = sC[(r0 + lane) * SC_LD + c] + bb;
                    C[(size_t)(n0 + c) * ldc + m0 + pass * 64 + r0 + lane] = __float2half(v);
                }
            }
        } else {
            const int r  = tid >> 5;            // 0..7
            const int c4 = (tid & 31) << 2;     // 0..124
            float4 bb = *reinterpret_cast<const float4*>(bias + n0 + c4);
            #pragma unroll
            for (int rr = 0; rr < 64; rr += 8) {
                const int row = r + rr;
                float4 v = *reinterpret_cast<float4*>(&sC[row * SC_LD + c4]);
                __half2 h0 = __floats2half2_rn(v.x + bb.x, v.y + bb.y);
                __half2 h1 = __floats2half2_rn(v.z + bb.z, v.w + bb.w);
                __half2* dst = reinterpret_cast<__half2*>(
                    C + (size_t)(m0 + pass * 64 + row) * ldc + n0 + c4);
                dst[0] = h0; dst[1] = h1;
            }
        }
    }
}

// ---------------- fp16 GEMM (scores, PV) — unchanged from R6 ----------------
template<bool CAUSAL_SKIP, bool KCAUSAL>
__global__ __launch_bounds__(NTH)
void tg(const __half* __restrict__ A, const __half* __restrict__ Bm,
        float* __restrict__ C,
        int lda, int ldb, int ldc, int K,
        long strideA, long strideB, long strideC, float scale)
{
    extern __shared__ __half sm[];

    const int m0 = blockIdx.x * BM;
    const int n0 = blockIdx.y * BN;
    if (CAUSAL_SKIP && n0 > m0) return;

    const int bz = blockIdx.z;
    const __half* Ab = A  + (size_t)bz * strideA;
    const __half* Bb = Bm + (size_t)bz * strideB;

    const int kEnd = KCAUSAL ? (m0 + BM) : K;
    const int nk   = kEnd / BKH;

    const int tid  = threadIdx.x;
    const int warp = tid >> 5;
    const int wm   = warp >> 1;
    const int wn   = warp & 1;

    const unsigned smBase = (unsigned)__cvta_generic_to_shared(sm);

    wmma::fragment<wmma::accumulator, 16, 16, 16, float> acc[4][4];
    #pragma unroll
    for (int i = 0; i < 4; i++)
        #pragma unroll
        for (int j = 0; j < 4; j++)
            wmma::fill_fragment(acc[i][j], 0.0f);

    auto loadStage = [&](int st, int k0) {
        const unsigned base = smBase + (unsigned)(st * STAGE_HALVES) * 2u;
        #pragma unroll
        for (int i = 0; i < 8; i++) {
            const int ci = i * NTH + tid;
            const int r = ci >> 3, c8 = (ci & 7) << 3;
            cpa16(base + (unsigned)(r * KP + c8) * 2u,
                  Ab + (size_t)(m0 + r) * lda + k0 + c8);
        }
        const unsigned baseB = base + (unsigned)(BM * KP) * 2u;
        #pragma unroll
        for (int i = 0; i < 8; i++) {
            const int ci = i * NTH + tid;
            const int r = ci >> 3, c8 = (ci & 7) << 3;
            cpa16(baseB + (unsigned)(r * KP + c8) * 2u,
                  Bb + (size_t)(n0 + r) * ldb + k0 + c8);
        }
        asm volatile("cp.async.commit_group;");
    };

    loadStage(0, 0);

    for (int kt = 0; kt < nk; kt++) {
        if (kt + 1 < nk) {
            loadStage((kt + 1) & 1, (kt + 1) * BKH);
            asm volatile("cp.async.wait_group 1;" ::: "memory");
        } else {
            asm volatile("cp.async.wait_group 0;" ::: "memory");
        }
        __syncthreads();

        const __half* a0 = sm + (kt & 1) * STAGE_HALVES;
        const __half* b0 = a0 + BM * KP;

        #pragma unroll
        for (int kk = 0; kk < BKH; kk += 16) {
            wmma::fragment<wmma::matrix_a, 16, 16, 16, __half, wmma::row_major> af[4];
            #pragma unroll
            for (int i = 0; i < 4; i++)
                wmma::load_matrix_sync(af[i], a0 + (wm * 64 + i * 16) * KP + kk, KP);
            #pragma unroll
            for (int j = 0; j < 4; j++) {
                wmma::fragment<wmma::matrix_b, 16, 16, 16, __half, wmma::col_major> bf;
                wmma::load_matrix_sync(bf, b0 + (wn * 64 + j * 16) * KP + kk, KP);
                #pragma unroll
                for (int i = 0; i < 4; i++)
                    wmma::mma_sync(acc[i][j], af[i], bf, acc[i][j]);
            }
        }
        __syncthreads();
    }

    float* sC = reinterpret_cast<float*>(sm);
    #pragma unroll
    for (int i = 0; i < 4; i++)
        #pragma unroll
        for (int j = 0; j < 4; j++)
            wmma::store_matrix_sync(sC + (wm * 64 + i * 16) * SC_LD + wn * 64 + j * 16,
                                    acc[i][j], SC_LD, wmma::mem_row_major);
    __syncthreads();

    {
        const int r  = tid >> 5;
        const int c4 = (tid & 31) << 2;
        float* Cb = C + (size_t)bz * strideC;
        #pragma unroll
        for (int rr = 0; rr < BM; rr += 4) {
            const int m = m0 + r + rr;
            float4 v = *reinterpret_cast<float4*>(&sC[(r + rr) * SC_LD + c4]);
            v.x *= scale; v.y *= scale; v.z *= scale; v.w *= scale;
            *reinterpret_cast<float4*>(Cb + (size_t)m * ldc + n0 + c4) = v;
        }
    }
}

// ---------------- fp32 -> fp16 convert (weights only now) ----------------
__global__ __launch_bounds__(256)
void f2h(const float* __restrict__ in, __half* __restrict__ out, int n4)
{
    int i = blockIdx.x * 256 + threadIdx.x;
    if (i < n4) {
        float4 v = reinterpret_cast<const float4*>(in)[i];
        __half2 h0 = __floats2half2_rn(v.x, v.y);
        __half2 h1 = __floats2half2_rn(v.z, v.w);
        reinterpret_cast<__half2*>(out)[2 * i + 0] = h0;
        reinterpret_cast<__half2*>(out)[2 * i + 1] = h1;
    }
}

// bout[e] = b[e] + dot(W[e,:], ctx)
__global__ __launch_bounds__(256)
void bias_prep(const float* __restrict__ W, const float* __restrict__ b,
               const float* __restrict__ ctx, float* __restrict__ bout)
{
    __shared__ float red[8];
    const int e = blockIdx.x;
    const int tid = threadIdx.x, lane = tid & 31, w = tid >> 5;
    float s = 0.f;
    for (int d = tid; d < DIM; d += 256) s += W[(size_t)e * DIM + d] * ctx[d];
    #pragma unroll
    for (int o = 16; o; o >>= 1) s += __shfl_xor_sync(0xffffffffu, s, o);
    if (lane == 0) red[w] = s;
    __syncthreads();
    if (tid == 0) {
        float t = 0.f;
        #pragma unroll
        for (int x = 0; x < 8; x++) t += red[x];
        bout[e] = b[e] + t;
    }
}

// Causal row softmax: fp32 scores in, fp16 probs out (zero-filled to 128 boundary)
__global__ __launch_bounds__(256)
void softmax_kernel(const float* __restrict__ S, __half* __restrict__ P)
{
    __shared__ float buf[SEQ];
    __shared__ float red[8];
    const int row = blockIdx.x;
    const int b   = row >> 11;
    const int i   = row & (SEQ - 1);
    const float* p = S + ((size_t)b * SEQ + i) * SEQ;
    __half* q = P + ((size_t)b * SEQ + i) * SEQ;
    const int len = i + 1;
    const int tid = threadIdx.x, lane = tid & 31, w = tid >> 5;

    float m = -1e30f;
    for (int j = tid; j < len; j += 256) { float v = p[j]; buf[j] = v; m = fmaxf(m, v); }
    #pragma unroll
    for (int o = 16; o; o >>= 1) m = fmaxf(m, __shfl_xor_sync(0xffffffffu, m, o));
    if (lane == 0) red[w] = m;
    __syncthreads();
    if (tid == 0) {
        float mm = red[0];
        #pragma unroll
        for (int x = 1; x < 8; x++) mm = fmaxf(mm, red[x]);
        red[0] = mm;
    }
    __syncthreads();
    m = red[0];
    __syncthreads();

    float s = 0.f;
    for (int j = tid; j < len; j += 256) { float e = __expf(buf[j] - m); buf[j] = e; s += e; }
    #pragma unroll
    for (int o = 16; o; o >>= 1) s += __shfl_xor_sync(0xffffffffu, s, o);
    if (lane == 0) red[w] = s;
    __syncthreads();
    if (tid == 0) {
        float ss = red[0];
        #pragma unroll
        for (int x = 1; x < 8; x++) ss += red[x];
        red[0] = ss;
    }
    __syncthreads();
    const float inv = 1.0f / red[0];

    const int zend = min(SEQ, ((i >> 7) + 1) << 7);
    for (int j = tid; j < zend; j += 256)
        q[j] = (j < len) ? __float2half(buf[j] * inv) : __float2half(0.0f);
}

extern "C" void kernel_launch(void* const* d_in, const int* in_sizes, int n_in,
                              void* d_out, int out_size)
{
    const float* query = (const float*)d_in[0];
    const float* key   = (const float*)d_in[1];
    const float* value = (const float*)d_in[2];
    const float* ctx   = (const float*)d_in[3];
    const float* Wq    = (const float*)d_in[4];
    const float* bq    = (const float*)d_in[5];
    const float* Wk    = (const float*)d_in[6];
    const float* bk    = (const float*)d_in[7];
    const float* Wv    = (const float*)d_in[8];
    const float* bv    = (const float*)d_in[9];
    float* out = (float*)d_out;

    float *pS, *pBias;
    __half *phP, *phQ, *phK, *phVt, *phWq, *phWk, *phWv;
    cudaGetSymbolAddress((void**)&pS,   g_S);
    cudaGetSymbolAddress((void**)&phP,  g_hP);
    cudaGetSymbolAddress((void**)&phQ,  g_hQ);
    cudaGetSymbolAddress((void**)&phK,  g_hK);
    cudaGetSymbolAddress((void**)&phVt, g_hVt);
    cudaGetSymbolAddress((void**)&phWq, g_hWq);
    cudaGetSymbolAddress((void**)&phWk, g_hWk);
    cudaGetSymbolAddress((void**)&phWv, g_hWv);
    cudaGetSymbolAddress((void**)&pBias, g_bias);

    cudaFuncSetAttribute(tg<true,  false>, cudaFuncAttributeMaxDynamicSharedMemorySize, SMEM_BYTES);
    cudaFuncSetAttribute(tg<false, true >, cudaFuncAttributeMaxDynamicSharedMemorySize, SMEM_BYTES);

    const int nW4 = DIM * DIM / 4;

    // ---- fork aux stream ----
    cudaStream_t s1 = 0;
    cudaEvent_t evFork = 0, evQK = 0, evJoin = 0;
    bool forked = false;
    if (cudaStreamCreateWithFlags(&s1, cudaStreamNonBlocking) == cudaSuccess) {
        cudaEventCreateWithFlags(&evFork, cudaEventDisableTiming);
        cudaEventCreateWithFlags(&evQK,   cudaEventDisableTiming);
        cudaEventCreateWithFlags(&evJoin, cudaEventDisableTiming);
        forked = (cudaEventRecord(evFork, 0) == cudaSuccess) &&
                 (cudaStreamWaitEvent(s1, evFork, 0) == cudaSuccess);
    }
    cudaStream_t sAux = forked ? s1 : 0;

    // submissions 1-5 (capture slot 6 must be the Q GEMM)
    bias_prep<<<DIM, 256>>>(Wq, bq, ctx, pBias);                 // 1
    bias_prep<<<DIM, 256>>>(Wk, bk, ctx, pBias + DIM);           // 2
    f2h<<<nW4 / 256, 256>>>(Wq, phWq, nW4);                      // 3
    f2h<<<nW4 / 256, 256>>>(Wk, phWk, nW4);                      // 4
    f2h<<<nW4 / 256, 256, 0, sAux>>>(Wv, phWv, nW4);             // 5 (aux)

    dim3 gp(MTOT / 128, DIM / 128, 1);
    // 6: Q projection (ncu capture target)
    ptg<false><<<gp, 256, PSMEM_BYTES>>>(query, phWq, pBias, phQ, DIM);
    // 7: K projection
    ptg<false><<<gp, 256, PSMEM_BYTES>>>(key, phWk, pBias + DIM, phK, DIM);

    if (forked) { cudaEventRecord(evQK, 0); cudaStreamWaitEvent(sAux, evQK, 0); }
    // 8: V projection (aux) -> transposed fp16 Vt, overlaps scores+softmax
    ptg<true><<<gp, 256, PSMEM_BYTES, sAux>>>(value, phWv, bv, phVt, MTOT);
    if (forked) cudaEventRecord(evJoin, sAux);

    // 9: scores = Q @ K^T * scale (causal block skip)
    dim3 gs(SEQ / 128, SEQ / 128, BATCH);
    tg<true, false><<<gs, NTH, SMEM_BYTES>>>(phQ, phK, pS,
        DIM, DIM, SEQ, DIM,
        (long)SEQ * DIM, (long)SEQ * DIM, (long)SEQ * SEQ, 0.03125f);

    // 10: causal softmax
    softmax_kernel<<<MTOT, 256>>>(pS, phP);

    if (forked) cudaStreamWaitEvent(0, evJoin, 0);

    // 11: out = P @ Vt^T (K limited by causality)
    dim3 gv(SEQ / 128, DIM / 128, BATCH);
    tg<false, true><<<gv, NTH, SMEM_BYTES>>>(phP, phVt, out,
        SEQ, MTOT, DIM, SEQ,
        (long)SEQ * SEQ, (long)SEQ, (long)SEQ * DIM, 1.0f);

    if (forked) {
        cudaEventDestroy(evFork);
        cudaEventDestroy(evQK);
        cudaEventDestroy(evJoin);
    }
    if (s1) cudaStreamDestroy(s1);
}